// round 9
// baseline (speedup 1.0000x reference)
#include <cuda_runtime.h>
#include <cstdint>

// Problem constants (fixed by the dataset)
#define D      1024   // bond dimension
#define NSYM   32     // physical dimension / alphabet
#define F      1024   // chain length
#define NCTA   128    // persistent grid (<= 148 SMs: single wave, spin-safe)
#define TPB    256    // 8 warps per CTA -> 1024 warps == D output columns

// Transposed cores, EXACT fp32: g_MT[s][j][i] = core[s][i][j]
// (fp16/bf16 storage fails: fixed rounding perturbation accumulates coherently
//  over 1024 reuses of the same 32 matrices -> rel_err 0.146 measured)
__device__ float g_MT[NSYM][D][D];

// Tagged ping-pong v buffers: {float value (lo 32), step tag (hi 32)} per entry,
// published/observed with single aligned 8-byte L2 transactions.
__device__ __align__(16) unsigned long long g_vbuf[2][D];

__device__ __forceinline__ unsigned long long ld_cg_u64(const unsigned long long* p) {
    unsigned long long v;
    asm volatile("ld.global.cg.b64 %0, [%1];" : "=l"(v) : "l"(p) : "memory");
    return v;
}
__device__ __forceinline__ void st_cg_u64(unsigned long long* p, unsigned long long v) {
    asm volatile("st.global.cg.b64 [%0], %1;" :: "l"(p), "l"(v) : "memory");
}
// Volatile v4 load: pins issue position (prefetch must issue BEFORE the poll).
__device__ __forceinline__ float4 ldg_cg_v4(const float4* p) {
    float4 r;
    asm volatile("ld.global.cg.v4.f32 {%0,%1,%2,%3}, [%4];"
                 : "=f"(r.x), "=f"(r.y), "=f"(r.z), "=f"(r.w) : "l"(p));
    return r;
}

// ---------------------------------------------------------------------------
// K1: transpose all 32 cores (fp32, coalesced via 32x32 smem tiles)
// ---------------------------------------------------------------------------
__global__ void transpose_kernel(const float* __restrict__ core) {
    __shared__ float tile[32][33];
    const int s  = blockIdx.z;
    const int i0 = blockIdx.y * 32;
    const int j0 = blockIdx.x * 32;
    const int tx = threadIdx.x, ty = threadIdx.y;

    const float* src = core + ((size_t)s * D + i0) * D + j0;
    #pragma unroll
    for (int r = 0; r < 32; r += 8)
        tile[ty + r][tx] = src[(size_t)(ty + r) * D + tx];
    __syncthreads();

    float* dst = &g_MT[s][j0][i0];
    #pragma unroll
    for (int r = 0; r < 32; r += 8)
        dst[(size_t)(ty + r) * D + tx] = tile[tx][ty + r];
}

// ---------------------------------------------------------------------------
// K2: init tagged v buffers. buf0 = {left_boundary, tag 0}; buf1 = invalid.
// ---------------------------------------------------------------------------
__global__ void init_kernel(const float* __restrict__ lb) {
    int j = blockIdx.x * blockDim.x + threadIdx.x;
    if (j < D) {
        g_vbuf[0][j] = (unsigned long long)__float_as_uint(lb[j]);
        g_vbuf[1][j] = 0xFFFFFFFF00000000ull;
    }
}

// ---------------------------------------------------------------------------
// One chain step (R2's PROVEN poll/publish protocol, unchanged):
//   (optionally) issue volatile register prefetch of step t+1's matrix row
//   barrier-coupled poll of tagged v_{t-1} -> stage sv -> barrier ->
//   dot from CURRENT register buffer (filled during step t-1) -> warp-reduce ->
//   lane0 publishes {v_t[j], t}.
// sv reuse safe: next step's sv writes happen after next poll's barrier.
// ---------------------------------------------------------------------------
__device__ __forceinline__ void chain_step(int t, bool prefetch,
                                           float4* cur, float4* nxt,
                                           float* sv, const int* sx,
                                           int tid, int lane, int warp, int j) {
    if (prefetch) {
        // matrix row for step t+1 (symbol x[t]); full step to cover DRAM latency
        const float4* row = reinterpret_cast<const float4*>(&g_MT[sx[t]][j][0]);
        #pragma unroll
        for (int k = 0; k < 8; ++k)
            nxt[k] = ldg_cg_v4(&row[k * 32 + lane]);
    }

    // ---- barrier-coupled poll (exact R2 structure, proven rel_err 0.0) ----
    const unsigned long long* src = g_vbuf[(t - 1) & 1];
    unsigned long long p[4];
    int ok;
    do {
        #pragma unroll
        for (int q = 0; q < 4; ++q)
            p[q] = ld_cg_u64(&src[tid * 4 + q]);
        ok = 1;
        #pragma unroll
        for (int q = 0; q < 4; ++q)
            ok &= ((unsigned)(p[q] >> 32) == (unsigned)(t - 1));
    } while (!__syncthreads_and(ok));

    #pragma unroll
    for (int q = 0; q < 4; ++q)
        sv[tid * 4 + q] = __uint_as_float((unsigned)p[q]);
    __syncthreads();

    // ---- dot(MT[s][j][:], v): matrix from registers, v from smem ----
    float acc = 0.f;
    #pragma unroll
    for (int k = 0; k < 8; ++k) {
        const float4 vv = *reinterpret_cast<const float4*>(&sv[k * 128 + lane * 4]);
        acc = fmaf(cur[k].x, vv.x, acc);
        acc = fmaf(cur[k].y, vv.y, acc);
        acc = fmaf(cur[k].z, vv.z, acc);
        acc = fmaf(cur[k].w, vv.w, acc);
    }
    #pragma unroll
    for (int off = 16; off; off >>= 1)
        acc += __shfl_xor_sync(0xFFFFFFFFu, acc, off);

    if (lane == 0) {
        unsigned long long outp =
            ((unsigned long long)(unsigned)t << 32) |
            (unsigned long long)__float_as_uint(acc);
        st_cg_u64(&g_vbuf[t & 1][j], outp);
    }
}

// ---------------------------------------------------------------------------
// K3: persistent chain kernel, depth-2 register-resident matrix pipeline.
// Warp w owns output column j = w. Matrix for step t lives in registers,
// loaded during step t-1 (a full step of lead hides DRAM latency; the 4MB/step
// chip-wide matrix stream overlaps the poll/dot/publish sync chain).
// ---------------------------------------------------------------------------
__global__ void __launch_bounds__(TPB, 1) chain_kernel(const int* __restrict__ x) {
    __shared__ float sv[D];
    __shared__ int   sx[F];

    const int tid  = threadIdx.x;
    const int warp = tid >> 5;
    const int lane = tid & 31;
    const int j    = blockIdx.x * (TPB / 32) + warp;

    for (int k = tid; k < F; k += TPB) sx[k] = x[k];
    __syncthreads();

    float4 A[8], B[8];

    // Prologue: matrix for step 1 (symbol x[0]) into A.
    {
        const float4* row = reinterpret_cast<const float4*>(&g_MT[sx[0]][j][0]);
        #pragma unroll
        for (int k = 0; k < 8; ++k)
            A[k] = ldg_cg_v4(&row[k * 32 + lane]);
    }

    // F even: pairs (1,2), (3,4), ..., (1023,1024). Prefetch for t+1 at every
    // step except the last (t+1 index sx[t] stays in-bounds: t <= 1023).
    for (int t = 1; t <= F; t += 2) {
        chain_step(t,     true,           A, B, sv, sx, tid, lane, warp, j);
        chain_step(t + 1, (t + 1) < F,    B, A, sv, sx, tid, lane, warp, j);
    }
}

// ---------------------------------------------------------------------------
// K4: final reduction  out = dot(v_F, right_boundary).  (F even -> buf 0)
// ---------------------------------------------------------------------------
__global__ void final_kernel(const float* __restrict__ rb, float* __restrict__ out) {
    __shared__ float red[32];
    const int tid = threadIdx.x;      // 1024 threads
    const unsigned long long p = g_vbuf[F & 1][tid];
    float acc = __uint_as_float((unsigned)p) * rb[tid];
    #pragma unroll
    for (int off = 16; off; off >>= 1)
        acc += __shfl_xor_sync(0xFFFFFFFFu, acc, off);
    if ((tid & 31) == 0) red[tid >> 5] = acc;
    __syncthreads();
    if (tid < 32) {
        float a = red[tid];
        #pragma unroll
        for (int off = 16; off; off >>= 1)
            a += __shfl_xor_sync(0xFFFFFFFFu, a, off);
        if (tid == 0) out[0] = a;
    }
}

// ---------------------------------------------------------------------------
// Inputs (metadata order): x [F] int32, core [d*D*D] f32, left_boundary [D] f32,
// right_boundary [D] f32. Output: 1 float.
// ---------------------------------------------------------------------------
extern "C" void kernel_launch(void* const* d_in, const int* in_sizes, int n_in,
                              void* d_out, int out_size) {
    const int*   x    = (const int*)  d_in[0];
    const float* core = (const float*)d_in[1];
    const float* lb   = (const float*)d_in[2];
    const float* rb   = (const float*)d_in[3];
    float*       out  = (float*)d_out;

    transpose_kernel<<<dim3(32, 32, 32), dim3(32, 8)>>>(core);
    init_kernel<<<1, D>>>(lb);
    chain_kernel<<<NCTA, TPB>>>(x);
    final_kernel<<<1, D>>>(rb, out);
}

// round 16
// speedup vs baseline: 1.9409x; 1.9409x over previous
#include <cuda_runtime.h>
#include <cstdint>

// Problem constants (fixed by the dataset)
#define D      1024   // bond dimension
#define NSYM   32     // physical dimension / alphabet
#define F      1024   // chain length
#define NCTA   128    // persistent grid (<= 148 SMs: single wave, spin-safe)
#define TPB    256    // 8 warps per CTA -> 1024 warps == D output columns

// Transposed cores, EXACT fp32: g_MT[s][j][i] = core[s][i][j]
// (reduced-precision storage fails: fixed rounding of the 32 reused matrices
//  accumulates coherently over 1024 steps -> 0.146 rel_err measured)
__device__ float g_MT[NSYM][D][D];

// Ping-pong value buffers (bare fp32, no tags) + global step counter.
// Protocol: values are read ONLY after the release/acquire counter proves all
// 128 CTAs published. No reliance on per-entry tag atomicity (5/5 failures).
__device__ __align__(16) float g_v[2][D];
__device__ unsigned g_ctr;

__device__ __forceinline__ float4 ld_cg_v4f(const float* p) {
    float4 r;
    asm volatile("ld.global.cg.v4.f32 {%0,%1,%2,%3}, [%4];"
                 : "=f"(r.x), "=f"(r.y), "=f"(r.z), "=f"(r.w) : "l"(p) : "memory");
    return r;
}
__device__ __forceinline__ void st_cg_f32(float* p, float v) {
    asm volatile("st.global.cg.f32 [%0], %1;" :: "l"(p), "f"(v) : "memory");
}
__device__ __forceinline__ unsigned ld_acquire_u32(const unsigned* p) {
    unsigned v;
    asm volatile("ld.acquire.gpu.global.u32 %0, [%1];" : "=r"(v) : "l"(p) : "memory");
    return v;
}
__device__ __forceinline__ void red_release_add(unsigned* p, unsigned v) {
    asm volatile("red.release.gpu.global.add.u32 [%0], %1;" :: "l"(p), "r"(v) : "memory");
}

// ---------------------------------------------------------------------------
// K1: transpose all 32 cores (fp32, coalesced via 32x32 smem tiles)
// ---------------------------------------------------------------------------
__global__ void transpose_kernel(const float* __restrict__ core) {
    __shared__ float tile[32][33];
    const int s  = blockIdx.z;
    const int i0 = blockIdx.y * 32;
    const int j0 = blockIdx.x * 32;
    const int tx = threadIdx.x, ty = threadIdx.y;

    const float* src = core + ((size_t)s * D + i0) * D + j0;
    #pragma unroll
    for (int r = 0; r < 32; r += 8)
        tile[ty + r][tx] = src[(size_t)(ty + r) * D + tx];
    __syncthreads();

    float* dst = &g_MT[s][j0][i0];
    #pragma unroll
    for (int r = 0; r < 32; r += 8)
        dst[(size_t)(ty + r) * D + tx] = tile[tx][ty + r];
}

// ---------------------------------------------------------------------------
// K2: init value buffer 0 = left_boundary; counter = 0 (each graph replay).
// ---------------------------------------------------------------------------
__global__ void init_kernel(const float* __restrict__ lb) {
    int j = blockIdx.x * blockDim.x + threadIdx.x;
    if (j < D) {
        g_v[0][j] = lb[j];
        g_v[1][j] = 0.f;
    }
    if (j == 0) g_ctr = 0u;
}

// ---------------------------------------------------------------------------
// K3: persistent chain kernel. Global warp w owns output column j = w.
// Step t:
//   prefetch MT[x[t-1]][j][:] into 32 registers (__ldg; completes during wait)
//   tid0: acquire-poll g_ctr >= 128*(t-1)   (all CTAs published step t-1)
//   B1: __syncthreads                        (counter condition holds CTA-wide)
//   all threads: one ld.cg.v4 of their 4 values of v_{t-1} -> stage sv[pb]
//   B2: __syncthreads                        (sv fully staged)
//   dot(regs, sv) -> warp shuffle reduce -> lane0: st.cg v_t[j]
//   B3: __syncthreads                        (all 8 publishes of this CTA done)
//   tid0: red.release.gpu.add(g_ctr, 1)      (release orders the stores)
// Skew bound: a CTA at step t implies every CTA finished t-1 -> ping-pong
// distance 2 on g_v is safe. Deterministic: math identical every run.
// ---------------------------------------------------------------------------
__global__ void __launch_bounds__(TPB, 1) chain_kernel(const int* __restrict__ x) {
    __shared__ float sv[2][D];
    __shared__ int   sx[F];

    const int tid  = threadIdx.x;
    const int warp = tid >> 5;
    const int lane = tid & 31;
    const int j    = blockIdx.x * (TPB / 32) + warp;

    for (int k = tid; k < F; k += TPB) sx[k] = x[k];
    __syncthreads();

    for (int t = 1; t <= F; ++t) {
        const int pb = (t - 1) & 1;

        // ---- depth-1 register prefetch of this step's matrix row ----
        const int s = sx[t - 1];
        const float4* row = reinterpret_cast<const float4*>(&g_MT[s][j][0]);
        float4 m[8];
        #pragma unroll
        for (int k = 0; k < 8; ++k)
            m[k] = __ldg(&row[k * 32 + lane]);

        // ---- wait: all 128 CTAs have published step t-1 ----
        if (tid == 0) {
            const unsigned want = 128u * (unsigned)(t - 1);
            while (ld_acquire_u32(&g_ctr) < want) { }
        }
        __syncthreads();   // B1

        // ---- single read of v_{t-1} values (proven complete), stage to smem ----
        const float4 vv = ld_cg_v4f(&g_v[pb][tid * 4]);
        *reinterpret_cast<float4*>(&sv[pb][tid * 4]) = vv;
        __syncthreads();   // B2

        // ---- dot(MT[s][j][:], v) : matrix from regs, v from smem ----
        const float* svb = sv[pb];
        float acc = 0.f;
        #pragma unroll
        for (int k = 0; k < 8; ++k) {
            const float4 v4 = *reinterpret_cast<const float4*>(&svb[k * 128 + lane * 4]);
            acc = fmaf(m[k].x, v4.x, acc);
            acc = fmaf(m[k].y, v4.y, acc);
            acc = fmaf(m[k].z, v4.z, acc);
            acc = fmaf(m[k].w, v4.w, acc);
        }
        #pragma unroll
        for (int off = 16; off; off >>= 1)
            acc += __shfl_xor_sync(0xFFFFFFFFu, acc, off);

        if (lane == 0)
            st_cg_f32(&g_v[t & 1][j], acc);

        __syncthreads();   // B3: all 8 warps' publishes issued before the bump
        if (tid == 0)
            red_release_add(&g_ctr, 1u);
    }
}

// ---------------------------------------------------------------------------
// K4: final reduction  out = dot(v_F, right_boundary).  (F even -> buf 0)
// Separate launch: stream ordering fully fences the chain kernel's writes.
// ---------------------------------------------------------------------------
__global__ void final_kernel(const float* __restrict__ rb, float* __restrict__ out) {
    __shared__ float red[32];
    const int tid = threadIdx.x;      // 1024 threads
    float acc = g_v[F & 1][tid] * rb[tid];
    #pragma unroll
    for (int off = 16; off; off >>= 1)
        acc += __shfl_xor_sync(0xFFFFFFFFu, acc, off);
    if ((tid & 31) == 0) red[tid >> 5] = acc;
    __syncthreads();
    if (tid < 32) {
        float a = red[tid];
        #pragma unroll
        for (int off = 16; off; off >>= 1)
            a += __shfl_xor_sync(0xFFFFFFFFu, a, off);
        if (tid == 0) out[0] = a;
    }
}

// ---------------------------------------------------------------------------
// Inputs (metadata order): x [F] int32, core [d*D*D] f32, left_boundary [D] f32,
// right_boundary [D] f32. Output: 1 float.
// ---------------------------------------------------------------------------
extern "C" void kernel_launch(void* const* d_in, const int* in_sizes, int n_in,
                              void* d_out, int out_size) {
    const int*   x    = (const int*)  d_in[0];
    const float* core = (const float*)d_in[1];
    const float* lb   = (const float*)d_in[2];
    const float* rb   = (const float*)d_in[3];
    float*       out  = (float*)d_out;

    transpose_kernel<<<dim3(32, 32, 32), dim3(32, 8)>>>(core);
    init_kernel<<<1, D>>>(lb);
    chain_kernel<<<NCTA, TPB>>>(x);
    final_kernel<<<1, D>>>(rb, out);
}